// round 4
// baseline (speedup 1.0000x reference)
#include <cuda_runtime.h>
#include <math.h>

#define NLAYER 12
#define NH 12
#define DH 64
#define DMODEL 768
#define DFF 3072
#define NV 10000
#define QLEN 512
#define MLEN 512
#define CLEN 32
#define BSZ 4
#define KLEN 1056               // CLEN + MLEN + QLEN
#define QB (QLEN*BSZ)           // 2048
#define KB (KLEN*BSZ)           // 4224
#define TND (3*NH*DH)           // 2304
#define ND (NH*DH)              // 768
#define NBATCH (BSZ*NH)         // 48

// ---------------- scratch (device globals; no allocation) ----------------
__device__ float g_h[QB*DMODEL];
__device__ float g_r[KLEN*DMODEL];
__device__ float g_heads[(size_t)KB*TND];
__device__ float g_rk[KLEN*DMODEL];
__device__ float g_ac[(size_t)NBATCH*QLEN*KLEN];
__device__ float g_bd[(size_t)NBATCH*QLEN*KLEN];
__device__ float g_av[QB*DMODEL];
__device__ float g_ff[(size_t)QB*DFF];

// ---------------- small helpers ----------------
__device__ __forceinline__ float warp_sum(float v) {
    #pragma unroll
    for (int o = 16; o; o >>= 1) v += __shfl_xor_sync(0xffffffffu, v, o);
    return v;
}
__device__ __forceinline__ float warp_max(float v) {
    #pragma unroll
    for (int o = 16; o; o >>= 1) v = fmaxf(v, __shfl_xor_sync(0xffffffffu, v, o));
    return v;
}
__device__ __forceinline__ float block_sum(float v, float* red) {
    v = warp_sum(v);
    __syncthreads();
    if ((threadIdx.x & 31) == 0) red[threadIdx.x >> 5] = v;
    __syncthreads();
    float r = 0.f;
    #pragma unroll
    for (int k = 0; k < 8; k++) r += red[k];
    return r;
}

// ---------------- embedding ----------------
__global__ void embed_kernel(const int* __restrict__ x, const float* __restrict__ emb) {
    int idx = blockIdx.x * 256 + threadIdx.x;
    if (idx >= QB * DMODEL) return;
    int row = idx / DMODEL, d = idx % DMODEL;
    int tok = x[row];
    g_h[idx] = emb[(size_t)tok * DMODEL + d] * sqrtf(768.0f);
}

// ---------------- sinusoidal relative position embedding ----------------
__global__ void posemb_kernel() {
    int idx = blockIdx.x * 256 + threadIdx.x;
    if (idx >= KLEN * DMODEL) return;
    int p = idx / DMODEL, d = idx % DMODEL;
    float pos = (float)(KLEN - 1 - p);
    int dd = (d < 384) ? d : d - 384;
    float inv = 1.0f / powf(10000.0f, (float)(2 * dd) / 768.0f);
    float s = pos * inv;
    g_r[idx] = (d < 384) ? sinf(s) : cosf(s);
}

// ---------------- big NN GEMM: 128x128 tile, 8x8 micro, double-buffered ----------------
// C[M,N] = A[M,K] @ B[K,N] (+bias)(+relu). K must be a multiple of 16, N a multiple of 4.
__global__ void __launch_bounds__(256, 2)
gemm128(const float* __restrict__ A, int lda,
        const float* __restrict__ B, int ldb,
        float* __restrict__ C, int ldc,
        int M, int N, int K,
        const float* __restrict__ bias, int relu)
{
    __shared__ float As[2][16][132];   // padded to kill transpose-store conflicts
    __shared__ float Bs[2][16][128];
    const int tid = threadIdx.x;
    const int row0 = blockIdx.y * 128, col0 = blockIdx.x * 128;
    const int ar  = tid >> 2;          // 0..63  (A staging row)
    const int acl = (tid & 3) << 2;    // 0,4,8,12 (A staging k-col)
    const int br  = tid >> 5;          // 0..7   (B staging k-row)
    const int bcl = (tid & 31) << 2;   // 0..124 (B staging col)
    const int ty4 = (tid >> 4) << 2;
    const int tx4 = (tid & 15) << 2;

    const bool aval0 = (row0 + ar) < M;
    const bool aval1 = (row0 + ar + 64) < M;
    const bool bval  = (col0 + bcl) < N;
    const float* Ap0 = A + (size_t)(row0 + ar) * lda + acl;
    const float* Ap1 = A + (size_t)(row0 + ar + 64) * lda + acl;
    const float* Bp0 = B + (size_t)br * ldb + col0 + bcl;
    const float* Bp1 = B + (size_t)(br + 8) * ldb + col0 + bcl;

    float acc[8][8] = {};
    const int KT = K >> 4;
    const float4 z4 = make_float4(0.f, 0.f, 0.f, 0.f);
    float4 fa0, fa1, fb0, fb1;

#define FETCH(k0) do { \
        fa0 = aval0 ? *(const float4*)(Ap0 + (k0)) : z4; \
        fa1 = aval1 ? *(const float4*)(Ap1 + (k0)) : z4; \
        fb0 = bval  ? *(const float4*)(Bp0 + (size_t)(k0) * ldb) : z4; \
        fb1 = bval  ? *(const float4*)(Bp1 + (size_t)(k0) * ldb) : z4; \
    } while (0)
#define STAGE(bf) do { \
        As[bf][acl+0][ar] = fa0.x; As[bf][acl+1][ar] = fa0.y; \
        As[bf][acl+2][ar] = fa0.z; As[bf][acl+3][ar] = fa0.w; \
        As[bf][acl+0][ar+64] = fa1.x; As[bf][acl+1][ar+64] = fa1.y; \
        As[bf][acl+2][ar+64] = fa1.z; As[bf][acl+3][ar+64] = fa1.w; \
        *(float4*)&Bs[bf][br][bcl]     = fb0; \
        *(float4*)&Bs[bf][br + 8][bcl] = fb1; \
    } while (0)

    FETCH(0); STAGE(0); __syncthreads();

    for (int kt = 0; kt < KT; kt++) {
        int buf = kt & 1;
        if (kt + 1 < KT) FETCH((kt + 1) << 4);
        #pragma unroll
        for (int k = 0; k < 16; k++) {
            float4 xa0 = *(const float4*)&As[buf][k][ty4];
            float4 xa1 = *(const float4*)&As[buf][k][ty4 + 64];
            float4 xb0 = *(const float4*)&Bs[buf][k][tx4];
            float4 xb1 = *(const float4*)&Bs[buf][k][tx4 + 64];
            float av8[8] = {xa0.x, xa0.y, xa0.z, xa0.w, xa1.x, xa1.y, xa1.z, xa1.w};
            float bv8[8] = {xb0.x, xb0.y, xb0.z, xb0.w, xb1.x, xb1.y, xb1.z, xb1.w};
            #pragma unroll
            for (int i = 0; i < 8; i++)
                #pragma unroll
                for (int j = 0; j < 8; j++) acc[i][j] += av8[i] * bv8[j];
        }
        if (kt + 1 < KT) { STAGE(buf ^ 1); __syncthreads(); }
    }
#undef FETCH
#undef STAGE

    #pragma unroll
    for (int i = 0; i < 8; i++) {
        int r = row0 + ty4 + ((i < 4) ? i : 60 + i);   // ty4 + i  or  ty4 + 64 + (i-4)
        if (r >= M) continue;
        #pragma unroll
        for (int j = 0; j < 8; j++) {
            int c = col0 + tx4 + ((j < 4) ? j : 60 + j);
            if (c >= N) continue;
            float v = acc[i][j];
            if (bias) v += bias[c];
            if (relu) v = fmaxf(v, 0.f);
            C[(size_t)r * ldc + c] = v;
        }
    }
}

// ---------------- fused attention scores: AC = (q+rwb)@k^T, BD = (q+rrb)@rk^T ----------------
// One block: 64 q-rows x 64 key-cols for one (b,n). q tile staged once, biases folded in.
__global__ void __launch_bounds__(256)
attn_scores(const float* __restrict__ heads, const float* __restrict__ rk,
            const float* __restrict__ rwb, const float* __restrict__ rrb,
            float* __restrict__ ac, float* __restrict__ bd)
{
    const int z = blockIdx.z, bb = z / NH, nn = z % NH;
    const float* q  = heads + (size_t)(CLEN + MLEN) * BSZ * TND + (size_t)bb * TND + nn * DH;
    const float* kk = heads + ND + (size_t)bb * TND + nn * DH;
    const float* rr = rk + nn * DH;
    const float* wb = rwb + nn * DH;
    const float* rb = rrb + nn * DH;
    const int row0 = blockIdx.y * 64, col0 = blockIdx.x * 64;

    __shared__ float Qw[32][68], Qr[32][68], Ks[32][68], Rs[32][68];
    const int tid = threadIdx.x;
    const int tx4 = (tid & 15) << 2, ty4 = (tid >> 4) << 2;
    float acc1[4][4] = {}, acc2[4][4] = {};

    for (int k0 = 0; k0 < DH; k0 += 32) {
        #pragma unroll
        for (int s = 0; s < 2; s++) {
            int idx = tid * 2 + s;              // 0..511
            int m = idx >> 3, c4 = (idx & 7) << 2;
            // q rows (always valid: QLEN multiple of 64)
            float4 qv = *(const float4*)(q + (size_t)(row0 + m) * (BSZ * TND) + k0 + c4);
            Qw[c4+0][m] = qv.x + wb[k0+c4+0]; Qw[c4+1][m] = qv.y + wb[k0+c4+1];
            Qw[c4+2][m] = qv.z + wb[k0+c4+2]; Qw[c4+3][m] = qv.w + wb[k0+c4+3];
            Qr[c4+0][m] = qv.x + rb[k0+c4+0]; Qr[c4+1][m] = qv.y + rb[k0+c4+1];
            Qr[c4+2][m] = qv.z + rb[k0+c4+2]; Qr[c4+3][m] = qv.w + rb[k0+c4+3];
            // key / rk cols (guard j < KLEN)
            int jj = col0 + m;
            float4 kv = make_float4(0,0,0,0), rv = make_float4(0,0,0,0);
            if (jj < KLEN) {
                kv = *(const float4*)(kk + (size_t)jj * (BSZ * TND) + k0 + c4);
                rv = *(const float4*)(rr + (size_t)jj * ND + k0 + c4);
            }
            Ks[c4+0][m] = kv.x; Ks[c4+1][m] = kv.y; Ks[c4+2][m] = kv.z; Ks[c4+3][m] = kv.w;
            Rs[c4+0][m] = rv.x; Rs[c4+1][m] = rv.y; Rs[c4+2][m] = rv.z; Rs[c4+3][m] = rv.w;
        }
        __syncthreads();
        #pragma unroll
        for (int k = 0; k < 32; k++) {
            float4 qa = *(const float4*)&Qw[k][ty4];
            float4 qb = *(const float4*)&Qr[k][ty4];
            float4 kv = *(const float4*)&Ks[k][tx4];
            float4 rv = *(const float4*)&Rs[k][tx4];
            float a1[4] = {qa.x, qa.y, qa.z, qa.w};
            float a2[4] = {qb.x, qb.y, qb.z, qb.w};
            float b1[4] = {kv.x, kv.y, kv.z, kv.w};
            float b2[4] = {rv.x, rv.y, rv.z, rv.w};
            #pragma unroll
            for (int i = 0; i < 4; i++)
                #pragma unroll
                for (int j = 0; j < 4; j++) {
                    acc1[i][j] += a1[i] * b1[j];
                    acc2[i][j] += a2[i] * b2[j];
                }
        }
        __syncthreads();
    }

    #pragma unroll
    for (int i = 0; i < 4; i++) {
        size_t rbase = ((size_t)z * QLEN + row0 + ty4 + i) * KLEN;
        #pragma unroll
        for (int j = 0; j < 4; j++) {
            int c = col0 + tx4 + j;
            if (c >= KLEN) continue;
            ac[rbase + c] = acc1[i][j];
            bd[rbase + c] = acc2[i][j];
        }
    }
}

// ---------------- av = prob @ v per (b,n): [512 x 1056] @ [1056 x 64] ----------------
__global__ void __launch_bounds__(256)
attn_av(const float* __restrict__ prob, const float* __restrict__ heads,
        float* __restrict__ av)
{
    const int z = blockIdx.z, bb = z / NH, nn = z % NH;
    const float* P = prob + (size_t)z * QLEN * KLEN;
    const float* V = heads + 2 * ND + (size_t)bb * TND + nn * DH;
    float* O = av + (size_t)bb * DMODEL + nn * DH;
    const int row0 = blockIdx.y * 64;

    __shared__ float Ps[32][68];  // [k][i]
    __shared__ float Vs[32][68];  // [k][d]
    const int tid = threadIdx.x;
    const int tx4 = (tid & 15) << 2, ty4 = (tid >> 4) << 2;
    float acc[4][4] = {};

    for (int k0 = 0; k0 < KLEN; k0 += 32) {
        #pragma unroll
        for (int s = 0; s < 2; s++) {
            int idx = tid * 2 + s;
            int m = idx >> 3, c4 = (idx & 7) << 2;
            float4 pv = *(const float4*)(P + (size_t)(row0 + m) * KLEN + k0 + c4);
            Ps[c4+0][m] = pv.x; Ps[c4+1][m] = pv.y; Ps[c4+2][m] = pv.z; Ps[c4+3][m] = pv.w;
            int kk_ = idx >> 4, c4v = (idx & 15) << 2;
            float4 vv = *(const float4*)(V + (size_t)(k0 + kk_) * (BSZ * TND) + c4v);
            *(float4*)&Vs[kk_][c4v] = vv;
        }
        __syncthreads();
        #pragma unroll
        for (int k = 0; k < 32; k++) {
            float4 pa = *(const float4*)&Ps[k][ty4];
            float4 vb = *(const float4*)&Vs[k][tx4];
            float a[4] = {pa.x, pa.y, pa.z, pa.w};
            float b[4] = {vb.x, vb.y, vb.z, vb.w};
            #pragma unroll
            for (int i = 0; i < 4; i++)
                #pragma unroll
                for (int j = 0; j < 4; j++) acc[i][j] += a[i] * b[j];
        }
        __syncthreads();
    }

    #pragma unroll
    for (int i = 0; i < 4; i++)
        #pragma unroll
        for (int j = 0; j < 4; j++)
            O[(size_t)(row0 + ty4 + i) * (BSZ * DMODEL) + tx4 + j] = acc[i][j];
}

// ---------------- masked softmax with rel-shift folded in ----------------
__global__ void __launch_bounds__(256) softmax_kernel() {
    int i = blockIdx.x, z = blockIdx.y;
    float* row = g_ac + ((size_t)z * QLEN + i) * KLEN;
    const float* bdrow = g_bd + ((size_t)z * QLEN + i) * KLEN;
    int jmax = i + CLEN + MLEN;      // inclusive
    __shared__ float s[KLEN];
    __shared__ float red[8];
    int tid = threadIdx.x;
    float lmax = -3.0e38f;
    for (int j = tid; j <= jmax; j += 256) {
        float v = (row[j] + bdrow[j + QLEN - 1 - i]) * 0.125f;
        s[j] = v;
        lmax = fmaxf(lmax, v);
    }
    lmax = warp_max(lmax);
    __syncthreads();
    if ((tid & 31) == 0) red[tid >> 5] = lmax;
    __syncthreads();
    float m = red[0];
    #pragma unroll
    for (int k = 1; k < 8; k++) m = fmaxf(m, red[k]);
    float lsum = 0.f;
    for (int j = tid; j <= jmax; j += 256) {
        float e = expf(s[j] - m);
        s[j] = e;
        lsum += e;
    }
    float total = block_sum(lsum, red);
    float inv = 1.0f / total;
    __syncthreads();
    for (int j = tid; j < KLEN; j += 256)
        row[j] = (j <= jmax) ? s[j] * inv : 0.0f;
}

// ---------------- h = LayerNorm(h + res) * g + b ----------------
__global__ void __launch_bounds__(256)
add_ln_kernel(float* __restrict__ h, const float* __restrict__ res,
              const float* __restrict__ g, const float* __restrict__ b)
{
    __shared__ float red[8];
    int row = blockIdx.x, tid = threadIdx.x;
    size_t base = (size_t)row * DMODEL;
    float x0 = h[base + tid]       + res[base + tid];
    float x1 = h[base + tid + 256] + res[base + tid + 256];
    float x2 = h[base + tid + 512] + res[base + tid + 512];
    float S = block_sum(x0 + x1 + x2, red);
    float mean = S * (1.0f / 768.0f);
    float d0 = x0 - mean, d1 = x1 - mean, d2 = x2 - mean;
    float V = block_sum(d0 * d0 + d1 * d1 + d2 * d2, red);
    float inv = rsqrtf(V * (1.0f / 768.0f) + 1e-5f);
    h[base + tid]       = d0 * inv * g[tid]       + b[tid];
    h[base + tid + 256] = d1 * inv * g[tid + 256] + b[tid + 256];
    h[base + tid + 512] = d2 * inv * g[tid + 512] + b[tid + 512];
}

// ---------------- host orchestration ----------------
extern "C" void kernel_launch(void* const* d_in, const int* in_sizes, int n_in,
                              void* d_out, int out_size)
{
    const int*   x         = (const int*)  d_in[0];
    const float* condition = (const float*)d_in[1];
    const float* mems      = (const float*)d_in[2];
    const float* emb       = (const float*)d_in[3];
    const float* qkv_w     = (const float*)d_in[4];
    const float* r_net_w   = (const float*)d_in[5];
    const float* o_w       = (const float*)d_in[6];
    const float* ln1_g     = (const float*)d_in[7];
    const float* ln1_b     = (const float*)d_in[8];
    const float* w1        = (const float*)d_in[9];
    const float* b1        = (const float*)d_in[10];
    const float* w2        = (const float*)d_in[11];
    const float* b2        = (const float*)d_in[12];
    const float* ln2_g     = (const float*)d_in[13];
    const float* ln2_b     = (const float*)d_in[14];
    const float* r_w_bias  = (const float*)d_in[15];
    const float* r_r_bias  = (const float*)d_in[16];
    const float* proj_w    = (const float*)d_in[17];
    const float* proj_b    = (const float*)d_in[18];
    float* out = (float*)d_out;

    float *h, *r, *heads, *rk, *ac, *bd, *av, *ff;
    cudaGetSymbolAddress((void**)&h,     g_h);
    cudaGetSymbolAddress((void**)&r,     g_r);
    cudaGetSymbolAddress((void**)&heads, g_heads);
    cudaGetSymbolAddress((void**)&rk,    g_rk);
    cudaGetSymbolAddress((void**)&ac,    g_ac);
    cudaGetSymbolAddress((void**)&bd,    g_bd);
    cudaGetSymbolAddress((void**)&av,    g_av);
    cudaGetSymbolAddress((void**)&ff,    g_ff);

    embed_kernel<<<(QB * DMODEL + 255) / 256, 256>>>(x, emb);
    posemb_kernel<<<(KLEN * DMODEL + 255) / 256, 256>>>();

    for (int l = 0; l < NLAYER; l++) {
        const float* W = qkv_w + (size_t)l * DMODEL * TND;

        // qkv projection of (condition | mems[l] | h). cond/mems rows only need k,v.
        gemm128<<<dim3(12, 1), 256>>>(condition, DMODEL, W + ND, TND,
                                      heads + ND, TND,
                                      CLEN * BSZ, 2 * ND, DMODEL, nullptr, 0);
        gemm128<<<dim3(12, 16), 256>>>(mems + (size_t)l * MLEN * BSZ * DMODEL, DMODEL,
                                       W + ND, TND,
                                       heads + (size_t)CLEN * BSZ * TND + ND, TND,
                                       MLEN * BSZ, 2 * ND, DMODEL, nullptr, 0);
        gemm128<<<dim3(18, 16), 256>>>(h, DMODEL, W, TND,
                                       heads + (size_t)(CLEN + MLEN) * BSZ * TND, TND,
                                       QB, TND, DMODEL, nullptr, 0);

        // rk = r @ r_net_w[l]   [KLEN, 768]
        gemm128<<<dim3(6, 9), 256>>>(r, DMODEL, r_net_w + (size_t)l * DMODEL * ND, ND,
                                     rk, ND, KLEN, ND, DMODEL, nullptr, 0);

        // fused AC / BD score GEMMs
        attn_scores<<<dim3(17, 8, NBATCH), 256>>>(heads, rk, r_w_bias, r_r_bias, ac, bd);

        softmax_kernel<<<dim3(QLEN, NBATCH), 256>>>();

        // av[i,b,n,:] = prob[z,i,:] @ v
        attn_av<<<dim3(1, 8, NBATCH), 256>>>(ac, heads, av);

        // attention output projection, residual + LN
        gemm128<<<dim3(6, 16), 256>>>(av, DMODEL, o_w + (size_t)l * ND * DMODEL, DMODEL,
                                      ff, DMODEL, QB, DMODEL, ND, nullptr, 0);
        add_ln_kernel<<<QB, 256>>>(h, ff, ln1_g + l * DMODEL, ln1_b + l * DMODEL);

        // FFN
        gemm128<<<dim3(24, 16), 256>>>(h, DMODEL, w1 + (size_t)l * DMODEL * DFF, DFF,
                                       ff, DFF, QB, DFF, DMODEL, b1 + (size_t)l * DFF, 1);
        gemm128<<<dim3(6, 16), 256>>>(ff, DFF, w2 + (size_t)l * DFF * DMODEL, DMODEL,
                                      av, DMODEL, QB, DMODEL, DFF, b2 + (size_t)l * DMODEL, 0);
        add_ln_kernel<<<QB, 256>>>(h, av, ln2_g + l * DMODEL, ln2_b + l * DMODEL);
    }

    // final projection to vocab
    gemm128<<<dim3((NV + 127) / 128, 16), 256>>>(h, DMODEL, proj_w, NV,
                                                 out, NV, QB, NV, DMODEL, proj_b, 0);
}

// round 6
// speedup vs baseline: 1.1205x; 1.1205x over previous
#include <cuda_runtime.h>
#include <math.h>
#include <stdint.h>

#define NLAYER 12
#define NH 12
#define DH 64
#define DMODEL 768
#define DFF 3072
#define NV 10000
#define QLEN 512
#define MLEN 512
#define CLEN 32
#define BSZ 4
#define KLEN 1056
#define QB (QLEN*BSZ)
#define KB (KLEN*BSZ)
#define TND (3*NH*DH)
#define ND (NH*DH)
#define NBATCH (BSZ*NH)

#if defined(__CUDA_ARCH_FEAT_SM103_ALL) || defined(__CUDA_ARCH_FEAT_SM100_ALL)
#define HAS_TC 1
#else
#define HAS_TC 0
#endif

// ---------------- scratch ----------------
__device__ float g_h[QB*DMODEL];
__device__ float g_r[KLEN*DMODEL];
__device__ float g_heads[(size_t)KB*TND];
__device__ float g_rk[KLEN*DMODEL];
__device__ float g_ac[(size_t)NBATCH*QLEN*KLEN];
__device__ float g_bd[(size_t)NBATCH*QLEN*KLEN];
__device__ float g_av[QB*DMODEL];
__device__ float g_ff[(size_t)QB*DFF];
__device__ __align__(16) unsigned short g_qkvT_h[(size_t)NLAYER*TND*DMODEL], g_qkvT_l[(size_t)NLAYER*TND*DMODEL];
__device__ __align__(16) unsigned short g_rnT_h[(size_t)NLAYER*ND*DMODEL],  g_rnT_l[(size_t)NLAYER*ND*DMODEL];
__device__ __align__(16) unsigned short g_oT_h[(size_t)NLAYER*DMODEL*ND],   g_oT_l[(size_t)NLAYER*DMODEL*ND];
__device__ __align__(16) unsigned short g_w1T_h[(size_t)NLAYER*DFF*DMODEL], g_w1T_l[(size_t)NLAYER*DFF*DMODEL];
__device__ __align__(16) unsigned short g_w2T_h[(size_t)NLAYER*DMODEL*DFF], g_w2T_l[(size_t)NLAYER*DMODEL*DFF];
__device__ __align__(16) unsigned short g_pT_h[(size_t)NV*DMODEL],          g_pT_l[(size_t)NV*DMODEL];
__device__ __align__(16) unsigned short g_kt_h[(size_t)KB*ND],              g_kt_l[(size_t)KB*ND];
__device__ __align__(16) unsigned short g_rkt_h[(size_t)KLEN*ND],           g_rkt_l[(size_t)KLEN*ND];
__device__ __align__(16) unsigned short g_vt_h[(size_t)NBATCH*DH*KLEN],     g_vt_l[(size_t)NBATCH*DH*KLEN];

// ---------------- PTX helpers ----------------
__device__ __forceinline__ uint32_t smem_u32(const void* p) {
    uint32_t a;
    asm("{ .reg .u64 t; cvta.to.shared.u64 t, %1; cvt.u32.u64 %0, t; }" : "=r"(a) : "l"(p));
    return a;
}
#define MBAR_INIT(a,c) asm volatile("mbarrier.init.shared.b64 [%0], %1;" :: "r"((uint32_t)(a)), "r"((uint32_t)(c)) : "memory")
#define MBAR_INVAL(a)  asm volatile("mbarrier.inval.shared.b64 [%0];" :: "r"((uint32_t)(a)) : "memory")
#define MBAR_WAIT(a,p) do { uint32_t _m=(uint32_t)(a), _p=(uint32_t)(p); \
    asm volatile("{\n\t.reg .pred P1;\n\tWL_%=:\n\t" \
        "mbarrier.try_wait.parity.acquire.cta.shared::cta.b64 P1, [%0], %1, 0x989680;\n\t" \
        "@P1 bra.uni WD_%=;\n\tbra.uni WL_%=;\n\tWD_%=:\n\t}" :: "r"(_m), "r"(_p) : "memory"); } while(0)
#define TC_ALLOC(a,n)   asm volatile("tcgen05.alloc.cta_group::1.sync.aligned.shared::cta.b32 [%0], %1;" :: "r"((uint32_t)(a)), "r"((uint32_t)(n)) : "memory")
#define TC_DEALLOC(t,n) asm volatile("tcgen05.dealloc.cta_group::1.sync.aligned.b32 %0, %1;" :: "r"(t), "r"((uint32_t)(n)))
#define TC_RELINQ()     asm volatile("tcgen05.relinquish_alloc_permit.cta_group::1.sync.aligned;")
#define TC_COMMIT(a)    asm volatile("tcgen05.commit.cta_group::1.mbarrier::arrive::one.shared::cluster.b64 [%0];" :: "r"((uint32_t)(a)) : "memory")
#define TC_WAIT_LD()    asm volatile("tcgen05.wait::ld.sync.aligned;" ::: "memory")
#define TC_FENCE_AFT()  asm volatile("tcgen05.fence::after_thread_sync;" ::: "memory")
#define FENCE_ASYNC()   asm volatile("fence.proxy.async.shared::cta;" ::: "memory")
#define TC_LD_X32(r, ta) asm volatile( \
    "tcgen05.ld.sync.aligned.32x32b.x32.b32 " \
    "{%0,%1,%2,%3,%4,%5,%6,%7,%8,%9,%10,%11,%12,%13,%14,%15," \
    "%16,%17,%18,%19,%20,%21,%22,%23,%24,%25,%26,%27,%28,%29,%30,%31}, [%32];" \
    : "=r"((r)[0]),"=r"((r)[1]),"=r"((r)[2]),"=r"((r)[3]),"=r"((r)[4]),"=r"((r)[5]),"=r"((r)[6]),"=r"((r)[7]), \
      "=r"((r)[8]),"=r"((r)[9]),"=r"((r)[10]),"=r"((r)[11]),"=r"((r)[12]),"=r"((r)[13]),"=r"((r)[14]),"=r"((r)[15]), \
      "=r"((r)[16]),"=r"((r)[17]),"=r"((r)[18]),"=r"((r)[19]),"=r"((r)[20]),"=r"((r)[21]),"=r"((r)[22]),"=r"((r)[23]), \
      "=r"((r)[24]),"=r"((r)[25]),"=r"((r)[26]),"=r"((r)[27]),"=r"((r)[28]),"=r"((r)[29]),"=r"((r)[30]),"=r"((r)[31]) \
    : "r"(ta))

static constexpr uint64_t DESC_BASE =
    (uint64_t(2) << 61) | (uint64_t(1) << 46) | (uint64_t(64) << 32) | (uint64_t(1) << 16);
#define MK_DESC(a) (DESC_BASE | ((uint64_t)((a) >> 4) & 0x3FFF))
#define IDESC_128 0x8200490u   // f32 accum, bf16 x bf16, M=128, N=128

#if HAS_TC
__device__ __forceinline__ void mma_bf16(uint32_t d, uint64_t ad, uint64_t bd, uint32_t en) {
    asm volatile(
        "{\n\t.reg .pred p;\n\tsetp.ne.u32 p, %4, 0;\n\t"
        "tcgen05.mma.cta_group::1.kind::f16 [%0], %1, %2, %3, {%5, %5, %5, %5}, p;\n\t}"
        :: "r"(d), "l"(ad), "l"(bd), "r"(IDESC_128), "r"(en), "r"(0u) : "memory");
}
#endif

__device__ __forceinline__ void split2(float x0, float x1, unsigned& hi, unsigned& lo) {
    unsigned u0 = __float_as_uint(x0), u1 = __float_as_uint(x1);
    unsigned r0 = (u0 + 0x7fffu + ((u0 >> 16) & 1u)) & 0xffff0000u;
    unsigned r1 = (u1 + 0x7fffu + ((u1 >> 16) & 1u)) & 0xffff0000u;
    hi = (r0 >> 16) | r1;
    unsigned v0 = __float_as_uint(x0 - __uint_as_float(r0));
    unsigned v1 = __float_as_uint(x1 - __uint_as_float(r1));
    unsigned s0 = (v0 + 0x7fffu + ((v0 >> 16) & 1u)) & 0xffff0000u;
    unsigned s1 = (v1 + 0x7fffu + ((v1 >> 16) & 1u)) & 0xffff0000u;
    lo = (s0 >> 16) | s1;
}
__device__ __forceinline__ void split1(float x, unsigned short& h, unsigned short& l) {
    unsigned u = __float_as_uint(x);
    unsigned r = (u + 0x7fffu + ((u >> 16) & 1u)) & 0xffff0000u;
    h = (unsigned short)(r >> 16);
    unsigned v = __float_as_uint(x - __uint_as_float(r));
    l = (unsigned short)((v + 0x7fffu + ((v >> 16) & 1u)) >> 16);
}
__device__ __forceinline__ float bfpair(unsigned short h, unsigned short l) {
    return __uint_as_float((unsigned)h << 16) + __uint_as_float((unsigned)l << 16);
}

__device__ __forceinline__ float warp_sum(float v) {
    #pragma unroll
    for (int o = 16; o; o >>= 1) v += __shfl_xor_sync(0xffffffffu, v, o);
    return v;
}
__device__ __forceinline__ float warp_max(float v) {
    #pragma unroll
    for (int o = 16; o; o >>= 1) v = fmaxf(v, __shfl_xor_sync(0xffffffffu, v, o));
    return v;
}
__device__ __forceinline__ float block_sum(float v, float* red) {
    v = warp_sum(v);
    __syncthreads();
    if ((threadIdx.x & 31) == 0) red[threadIdx.x >> 5] = v;
    __syncthreads();
    float r = 0.f;
    #pragma unroll
    for (int k = 0; k < 8; k++) r += red[k];
    return r;
}

// ---------------- elementwise ----------------
__global__ void embed_kernel(const int* __restrict__ x, const float* __restrict__ emb) {
    int idx = blockIdx.x * 256 + threadIdx.x;
    if (idx >= QB * DMODEL) return;
    int row = idx / DMODEL, d = idx % DMODEL;
    g_h[idx] = emb[(size_t)x[row] * DMODEL + d] * sqrtf(768.0f);
}
__global__ void posemb_kernel() {
    int idx = blockIdx.x * 256 + threadIdx.x;
    if (idx >= KLEN * DMODEL) return;
    int p = idx / DMODEL, d = idx % DMODEL;
    float pos = (float)(KLEN - 1 - p);
    int dd = (d < 384) ? d : d - 384;
    float s = pos / powf(10000.0f, (float)(2 * dd) / 768.0f);
    g_r[idx] = (d < 384) ? sinf(s) : cosf(s);
}

// transpose+split: dst[z][c][r] = split(src[z][r][c])
__global__ void __launch_bounds__(256)
transpose_split(const float* __restrict__ src, int ldsrc, int rows, int cols,
                int zq, long srcOffB, long srcOffN,
                unsigned short* __restrict__ dhi, unsigned short* __restrict__ dlo,
                int lddst, long dstOffZ)
{
    __shared__ float t[32][33];
    int z = blockIdx.z, bb = z / zq, nn = z % zq;
    const float* s = src + (long)bb * srcOffB + (long)nn * srcOffN;
    unsigned short* dh = dhi + (long)z * dstOffZ;
    unsigned short* dl = dlo + (long)z * dstOffZ;
    int c0 = blockIdx.x * 32, r0 = blockIdx.y * 32;
    int tx = threadIdx.x & 31, ty = threadIdx.x >> 5;
    #pragma unroll
    for (int dy = 0; dy < 4; dy++) {
        int r = r0 + ty + dy * 8;
        t[ty + dy * 8][tx] = (r < rows && c0 + tx < cols) ? s[(long)r * ldsrc + c0 + tx] : 0.f;
    }
    __syncthreads();
    #pragma unroll
    for (int dy = 0; dy < 4; dy++) {
        int dr = c0 + ty + dy * 8, dc = r0 + tx;
        if (dr < cols && dc < rows) {
            unsigned short h, l;
            split1(t[tx][ty + dy * 8], h, l);
            dh[(long)dr * lddst + dc] = h;
            dl[(long)dr * lddst + dc] = l;
        }
    }
}

__global__ void __launch_bounds__(256)
split_strided(const float* __restrict__ src, int ld, int off, int width, long total,
              unsigned short* __restrict__ dhi, unsigned short* __restrict__ dlo)
{
    long i = ((long)blockIdx.x * 256 + threadIdx.x) * 4;
    if (i >= total) return;
    long row = i / width; int c = (int)(i % width);
    float4 v = *(const float4*)(src + row * ld + off + c);
    unsigned short h, l;
    split1(v.x, h, l); dhi[i] = h; dlo[i] = l;
    split1(v.y, h, l); dhi[i+1] = h; dlo[i+1] = l;
    split1(v.z, h, l); dhi[i+2] = h; dlo[i+2] = l;
    split1(v.w, h, l); dhi[i+3] = h; dlo[i+3] = l;
}

// ---------------- GEMM: C[z] = (A[z]+abias) @ B[z]^T  (B pre-split bf16 hi/lo) ----------------
#define TILE_B 16384
#define GT_SMEM (1024 + 8 * TILE_B)

__global__ void __launch_bounds__(256)
gemm_tc(const float* __restrict__ A, int lda, long aOffB, long aOffN,
        const float* __restrict__ abias, int abStrideN,
        const unsigned short* __restrict__ Bhi, const unsigned short* __restrict__ Blo,
        int ldb, long bOffB, long bOffN,
        float* __restrict__ C, int ldc, long cOffB, long cOffN,
        int M, int N, int K,
        const float* __restrict__ cbias, int relu)
{
    extern __shared__ char smem[];
    const int tid = threadIdx.x;
    const int bb = blockIdx.z / NH, nn = blockIdx.z % NH;
    const int row0 = blockIdx.y * 128, col0 = blockIdx.x * 128;
    const float* Az = A + (long)bb * aOffB + (long)nn * aOffN;
    const unsigned short* Bh = Bhi + (long)bb * bOffB + (long)nn * bOffN;
    const unsigned short* Bl = Blo + (long)bb * bOffB + (long)nn * bOffN;
    float* Cz = C + (long)bb * cOffB + (long)nn * cOffN;
    const float* ab = abias ? (abias + (long)nn * abStrideN) : (const float*)0;

#if HAS_TC
    const uint32_t sb = smem_u32(smem);
    const int wid = tid >> 5, lane = tid & 31;
    if (wid == 0) TC_ALLOC(sb, 128);
    if (tid == 0) { MBAR_INIT(sb + 16, 1); MBAR_INIT(sb + 24, 1); }
    __syncthreads();
    uint32_t tmem;
    asm volatile("ld.shared.b32 %0, [%1];" : "=r"(tmem) : "r"(sb));

    const int KT = (K + 63) >> 6;
    int ph0 = 0, ph1 = 0;

    for (int t = 0; t < KT; t++) {
        const int buf = t & 1;
        const uint32_t base = 1024 + (uint32_t)buf * 4 * TILE_B;
        if (t >= 2) {
            if (buf == 0) { MBAR_WAIT(sb + 16, ph0 & 1); ph0++; }
            else          { MBAR_WAIT(sb + 24, ph1 & 1); ph1++; }
        }
        const int k0 = t << 6;
        #pragma unroll
        for (int g = 0; g < 4; g++) {
            int gi = tid + g * 256;
            int r = gi >> 3, kg = gi & 7, kb = k0 + kg * 8;
            float xv[8] = {0,0,0,0,0,0,0,0};
            if (row0 + r < M && kb < K) {
                const float* p = Az + (long)(row0 + r) * lda + kb;
                float4 v0 = *(const float4*)p, v1 = *(const float4*)(p + 4);
                xv[0]=v0.x; xv[1]=v0.y; xv[2]=v0.z; xv[3]=v0.w;
                xv[4]=v1.x; xv[5]=v1.y; xv[6]=v1.z; xv[7]=v1.w;
                if (ab) {
                    #pragma unroll
                    for (int j = 0; j < 8; j++) xv[j] += ab[kb + j];
                }
            }
            unsigned h[4], l[4];
            #pragma unroll
            for (int j = 0; j < 4; j++) split2(xv[2*j], xv[2*j+1], h[j], l[j]);
            uint32_t bo = ((uint32_t)r << 7) + ((uint32_t)kg << 4);
            uint32_t sw = bo ^ ((bo >> 3) & 0x70);
            *(uint4*)(smem + base + sw)          = make_uint4(h[0], h[1], h[2], h[3]);
            *(uint4*)(smem + base + TILE_B + sw) = make_uint4(l[0], l[1], l[2], l[3]);
        }
        #pragma unroll
        for (int g = 0; g < 4; g++) {
            int gi = tid + g * 256;
            int n = gi >> 3, kg = gi & 7, kb = k0 + kg * 8;
            uint4 vh = make_uint4(0,0,0,0), vl = make_uint4(0,0,0,0);
            if (col0 + n < N && kb < K) {
                vh = *(const uint4*)(Bh + (long)(col0 + n) * ldb + kb);
                vl = *(const uint4*)(Bl + (long)(col0 + n) * ldb + kb);
            }
            uint32_t bo = ((uint32_t)n << 7) + ((uint32_t)kg << 4);
            uint32_t sw = bo ^ ((bo >> 3) & 0x70);
            *(uint4*)(smem + base + 2*TILE_B + sw) = vh;
            *(uint4*)(smem + base + 3*TILE_B + sw) = vl;
        }
        __syncthreads();
        if (tid == 0) {
            FENCE_ASYNC();
            uint64_t dAh = MK_DESC(sb + base);
            uint64_t dAl = MK_DESC(sb + base + TILE_B);
            uint64_t dBh = MK_DESC(sb + base + 2*TILE_B);
            uint64_t dBl = MK_DESC(sb + base + 3*TILE_B);
            #pragma unroll
            for (int ks = 0; ks < 4; ks++) {
                mma_bf16(tmem, dAh + ks*2, dBh + ks*2, (t > 0 || ks > 0) ? 1u : 0u);
                mma_bf16(tmem, dAh + ks*2, dBl + ks*2, 1u);
                mma_bf16(tmem, dAl + ks*2, dBh + ks*2, 1u);
            }
            if (buf == 0) TC_COMMIT(sb + 16); else TC_COMMIT(sb + 24);
        }
        __syncthreads();
    }
    if (KT >= 2) {
        if (((KT - 2) & 1) == 0) { MBAR_WAIT(sb + 16, ph0 & 1); ph0++; }
        else                     { MBAR_WAIT(sb + 24, ph1 & 1); ph1++; }
    }
    if (((KT - 1) & 1) == 0) { MBAR_WAIT(sb + 16, ph0 & 1); ph0++; }
    else                     { MBAR_WAIT(sb + 24, ph1 & 1); ph1++; }
    TC_FENCE_AFT();

    {
        int sub = wid & 3, ch = wid >> 2;
        int r = row0 + sub * 32 + lane;
        #pragma unroll
        for (int half = 0; half < 2; half++) {
            uint32_t dr[32];
            TC_LD_X32(dr, tmem + (uint32_t)(ch * 64 + half * 32));
            TC_WAIT_LD();
            if (r < M) {
                #pragma unroll
                for (int c = 0; c < 32; c++) {
                    int col = col0 + ch * 64 + half * 32 + c;
                    if (col < N) {
                        float v = __uint_as_float(dr[c]);
                        if (cbias) v += cbias[col];
                        if (relu) v = fmaxf(v, 0.f);
                        Cz[(long)r * ldc + col] = v;
                    }
                }
            }
        }
    }
    __syncthreads();
    if (tid == 0) { MBAR_INVAL(sb + 16); MBAR_INVAL(sb + 24); }
    if (wid == 0) { TC_RELINQ(); TC_DEALLOC(tmem, 128); }
#else
    // ---------- SIMT fallback (compute_103 pass; no tcgen05) ----------
    float* As = (float*)smem;              // [16][132] transposed A
    float* Bs = (float*)smem + 16 * 132;   // [16][128]
    const int ty4 = (tid >> 4) << 2, tx4 = (tid & 15) << 2;
    float acc[8][8] = {};
    for (int k0 = 0; k0 < K; k0 += 16) {
        #pragma unroll
        for (int s = 0; s < 2; s++) {
            int idx = tid + s * 256;               // 0..511
            int m = idx >> 2, kc = (idx & 3) << 2;
            float4 v = make_float4(0,0,0,0);
            if (row0 + m < M && k0 + kc < K)
                v = *(const float4*)(Az + (long)(row0 + m) * lda + k0 + kc);
            if (ab && k0 + kc < K) {
                v.x += ab[k0+kc]; v.y += ab[k0+kc+1]; v.z += ab[k0+kc+2]; v.w += ab[k0+kc+3];
            }
            As[(kc+0)*132+m] = v.x; As[(kc+1)*132+m] = v.y;
            As[(kc+2)*132+m] = v.z; As[(kc+3)*132+m] = v.w;
        }
        #pragma unroll
        for (int s = 0; s < 8; s++) {
            int idx = tid + s * 256;               // 0..2047
            int n = idx >> 4, kk2 = idx & 15;
            float v = 0.f;
            if (col0 + n < N && k0 + kk2 < K) {
                long o = (long)(col0 + n) * ldb + k0 + kk2;
                v = bfpair(Bh[o], Bl[o]);
            }
            Bs[kk2 * 128 + n] = v;
        }
        __syncthreads();
        #pragma unroll
        for (int k = 0; k < 16; k++) {
            float4 xa0 = *(const float4*)&As[k*132 + ty4];
            float4 xa1 = *(const float4*)&As[k*132 + ty4 + 64];
            float4 xb0 = *(const float4*)&Bs[k*128 + tx4];
            float4 xb1 = *(const float4*)&Bs[k*128 + tx4 + 64];
            float av8[8] = {xa0.x,xa0.y,xa0.z,xa0.w, xa1.x,xa1.y,xa1.z,xa1.w};
            float bv8[8] = {xb0.x,xb0.y,xb0.z,xb0.w, xb1.x,xb1.y,xb1.z,xb1.w};
            #pragma unroll
            for (int i = 0; i < 8; i++)
                #pragma unroll
                for (int j = 0; j < 8; j++) acc[i][j] += av8[i] * bv8[j];
        }
        __syncthreads();
    }
    #pragma unroll
    for (int i = 0; i < 8; i++) {
        int r = row0 + ty4 + ((i < 4) ? i : 60 + i);
        if (r >= M) continue;
        #pragma unroll
        for (int j = 0; j < 8; j++) {
            int c = col0 + tx4 + ((j < 4) ? j : 60 + j);
            if (c >= N) continue;
            float v = acc[i][j];
            if (cbias) v += cbias[c];
            if (relu) v = fmaxf(v, 0.f);
            Cz[(long)r * ldc + c] = v;
        }
    }
#endif
}

// ---------------- softmax (rel-shift folded) ----------------
__global__ void __launch_bounds__(256) softmax_kernel() {
    int i = blockIdx.x, z = blockIdx.y;
    float* row = g_ac + ((size_t)z * QLEN + i) * KLEN;
    const float* bdrow = g_bd + ((size_t)z * QLEN + i) * KLEN;
    int jmax = i + CLEN + MLEN;
    __shared__ float s[KLEN];
    __shared__ float red[8];
    int tid = threadIdx.x;
    float lmax = -3.0e38f;
    for (int j = tid; j <= jmax; j += 256) {
        float v = (row[j] + bdrow[j + QLEN - 1 - i]) * 0.125f;
        s[j] = v;
        lmax = fmaxf(lmax, v);
    }
    lmax = warp_max(lmax);
    __syncthreads();
    if ((tid & 31) == 0) red[tid >> 5] = lmax;
    __syncthreads();
    float m = red[0];
    #pragma unroll
    for (int k = 1; k < 8; k++) m = fmaxf(m, red[k]);
    float lsum = 0.f;
    for (int j = tid; j <= jmax; j += 256) { float e = expf(s[j] - m); s[j] = e; lsum += e; }
    float inv = 1.0f / block_sum(lsum, red);
    __syncthreads();
    for (int j = tid; j < KLEN; j += 256)
        row[j] = (j <= jmax) ? s[j] * inv : 0.0f;
}

__global__ void __launch_bounds__(256)
add_ln_kernel(float* __restrict__ h, const float* __restrict__ res,
              const float* __restrict__ g, const float* __restrict__ b)
{
    __shared__ float red[8];
    int row = blockIdx.x, tid = threadIdx.x;
    size_t base = (size_t)row * DMODEL;
    float x0 = h[base + tid]       + res[base + tid];
    float x1 = h[base + tid + 256] + res[base + tid + 256];
    float x2 = h[base + tid + 512] + res[base + tid + 512];
    float mean = block_sum(x0 + x1 + x2, red) * (1.0f / 768.0f);
    float d0 = x0 - mean, d1 = x1 - mean, d2 = x2 - mean;
    float inv = rsqrtf(block_sum(d0*d0 + d1*d1 + d2*d2, red) * (1.0f / 768.0f) + 1e-5f);
    h[base + tid]       = d0 * inv * g[tid]       + b[tid];
    h[base + tid + 256] = d1 * inv * g[tid + 256] + b[tid + 256];
    h[base + tid + 512] = d2 * inv * g[tid + 512] + b[tid + 512];
}

// ---------------- host ----------------
extern "C" void kernel_launch(void* const* d_in, const int* in_sizes, int n_in,
                              void* d_out, int out_size)
{
    const int*   x         = (const int*)  d_in[0];
    const float* condition = (const float*)d_in[1];
    const float* mems      = (const float*)d_in[2];
    const float* emb       = (const float*)d_in[3];
    const float* qkv_w     = (const float*)d_in[4];
    const float* r_net_w   = (const float*)d_in[5];
    const float* o_w       = (const float*)d_in[6];
    const float* ln1_g     = (const float*)d_in[7];
    const float* ln1_b     = (const float*)d_in[8];
    const float* w1        = (const float*)d_in[9];
    const float* b1        = (const float*)d_in[10];
    const float* w2        = (const float*)d_in[11];
    const float* b2        = (const float*)d_in[12];
    const float* ln2_g     = (const float*)d_in[13];
    const float* ln2_b     = (const float*)d_in[14];
    const float* r_w_bias  = (const float*)d_in[15];
    const float* r_r_bias  = (const float*)d_in[16];
    const float* proj_w    = (const float*)d_in[17];
    const float* proj_b    = (const float*)d_in[18];
    float* out = (float*)d_out;

    cudaFuncSetAttribute(gemm_tc, cudaFuncAttributeMaxDynamicSharedMemorySize, GT_SMEM);

    float *h, *r, *heads, *rk, *ac, *bd, *av, *ff;
    unsigned short *qkvTh,*qkvTl,*rnTh,*rnTl,*oTh,*oTl,*w1Th,*w1Tl,*w2Th,*w2Tl,*pTh,*pTl,*kth,*ktl,*rkth,*rktl,*vth,*vtl;
#define SYM(p, s) cudaGetSymbolAddress((void**)&p, s)
    SYM(h,g_h); SYM(r,g_r); SYM(heads,g_heads); SYM(rk,g_rk); SYM(ac,g_ac); SYM(bd,g_bd);
    SYM(av,g_av); SYM(ff,g_ff);
    SYM(qkvTh,g_qkvT_h); SYM(qkvTl,g_qkvT_l); SYM(rnTh,g_rnT_h); SYM(rnTl,g_rnT_l);
    SYM(oTh,g_oT_h); SYM(oTl,g_oT_l); SYM(w1Th,g_w1T_h); SYM(w1Tl,g_w1T_l);
    SYM(w2Th,g_w2T_h); SYM(w2Tl,g_w2T_l); SYM(pTh,g_pT_h); SYM(pTl,g_pT_l);
    SYM(kth,g_kt_h); SYM(ktl,g_kt_l); SYM(rkth,g_rkt_h); SYM(rktl,g_rkt_l);
    SYM(vth,g_vt_h); SYM(vtl,g_vt_l);
#undef SYM

    embed_kernel<<<(QB*DMODEL+255)/256, 256>>>(x, emb);
    posemb_kernel<<<(KLEN*DMODEL+255)/256, 256>>>();

    // weight transpose+split (hi/lo bf16)
    transpose_split<<<dim3(72,24,NLAYER),256>>>(qkv_w, TND, DMODEL, TND, 1, (long)DMODEL*TND, 0, qkvTh, qkvTl, DMODEL, (long)TND*DMODEL);
    transpose_split<<<dim3(24,24,NLAYER),256>>>(r_net_w, ND, DMODEL, ND, 1, (long)DMODEL*ND, 0, rnTh, rnTl, DMODEL, (long)ND*DMODEL);
    transpose_split<<<dim3(24,24,NLAYER),256>>>(o_w, DMODEL, ND, DMODEL, 1, (long)ND*DMODEL, 0, oTh, oTl, ND, (long)DMODEL*ND);
    transpose_split<<<dim3(96,24,NLAYER),256>>>(w1, DFF, DMODEL, DFF, 1, (long)DMODEL*DFF, 0, w1Th, w1Tl, DMODEL, (long)DFF*DMODEL);
    transpose_split<<<dim3(24,96,NLAYER),256>>>(w2, DMODEL, DFF, DMODEL, 1, (long)DFF*DMODEL, 0, w2Th, w2Tl, DFF, (long)DMODEL*DFF);
    transpose_split<<<dim3(313,24,1),256>>>(proj_w, NV, DMODEL, NV, 1, 0, 0, pTh, pTl, DMODEL, 0);

    for (int l = 0; l < NLAYER; l++) {
        const unsigned short* Wh = qkvTh + (size_t)l*TND*DMODEL;
        const unsigned short* Wl = qkvTl + (size_t)l*TND*DMODEL;
        float* q = heads + (size_t)(CLEN+MLEN)*BSZ*TND;

        gemm_tc<<<dim3(18,16,1),256,GT_SMEM>>>(h, DMODEL,0,0, 0,0, Wh, Wl, DMODEL,0,0,
            q, TND,0,0, QB, TND, DMODEL, 0,0);
        gemm_tc<<<dim3(12,1,1),256,GT_SMEM>>>(condition, DMODEL,0,0, 0,0,
            Wh + (size_t)ND*DMODEL, Wl + (size_t)ND*DMODEL, DMODEL,0,0,
            heads + ND, TND,0,0, CLEN*BSZ, 2*ND, DMODEL, 0,0);
        gemm_tc<<<dim3(12,16,1),256,GT_SMEM>>>(mems + (size_t)l*MLEN*BSZ*DMODEL, DMODEL,0,0, 0,0,
            Wh + (size_t)ND*DMODEL, Wl + (size_t)ND*DMODEL, DMODEL,0,0,
            heads + (size_t)CLEN*BSZ*TND + ND, TND,0,0, MLEN*BSZ, 2*ND, DMODEL, 0,0);
        gemm_tc<<<dim3(6,9,1),256,GT_SMEM>>>(r, DMODEL,0,0, 0,0,
            rnTh + (size_t)l*ND*DMODEL, rnTl + (size_t)l*ND*DMODEL, DMODEL,0,0,
            rk, ND,0,0, KLEN, ND, DMODEL, 0,0);

        split_strided<<<((long)KB*ND/4+255)/256,256>>>(heads, TND, ND, ND, (long)KB*ND, kth, ktl);
        split_strided<<<((long)KLEN*ND/4+255)/256,256>>>(rk, ND, 0, ND, (long)KLEN*ND, rkth, rktl);
        transpose_split<<<dim3(2,33,NBATCH),256>>>(heads + 2*ND, BSZ*TND, KLEN, DH, NH, TND, DH,
            vth, vtl, KLEN, (long)DH*KLEN);

        gemm_tc<<<dim3(9,4,NBATCH),256,GT_SMEM>>>(q, BSZ*TND, TND, DH, r_w_bias, DH,
            kth, ktl, BSZ*ND, ND, DH,
            ac, KLEN, (long)NH*QLEN*KLEN, (long)QLEN*KLEN, QLEN, KLEN, DH, 0,0);
        gemm_tc<<<dim3(9,4,NBATCH),256,GT_SMEM>>>(q, BSZ*TND, TND, DH, r_r_bias, DH,
            rkth, rktl, ND, 0, DH,
            bd, KLEN, (long)NH*QLEN*KLEN, (long)QLEN*KLEN, QLEN, KLEN, DH, 0,0);

        softmax_kernel<<<dim3(QLEN,NBATCH),256>>>();

        gemm_tc<<<dim3(1,4,NBATCH),256,GT_SMEM>>>(ac, KLEN, (long)NH*QLEN*KLEN, (long)QLEN*KLEN, 0,0,
            vth, vtl, KLEN, (long)NH*DH*KLEN, (long)DH*KLEN,
            av, BSZ*DMODEL, DMODEL, DH, QLEN, DH, KLEN, 0,0);

        gemm_tc<<<dim3(6,16,1),256,GT_SMEM>>>(av, DMODEL,0,0, 0,0,
            oTh + (size_t)l*DMODEL*ND, oTl + (size_t)l*DMODEL*ND, ND,0,0,
            ff, DMODEL,0,0, QB, DMODEL, ND, 0,0);
        add_ln_kernel<<<QB,256>>>(h, ff, ln1_g + l*DMODEL, ln1_b + l*DMODEL);

        gemm_tc<<<dim3(24,16,1),256,GT_SMEM>>>(h, DMODEL,0,0, 0,0,
            w1Th + (size_t)l*DFF*DMODEL, w1Tl + (size_t)l*DFF*DMODEL, DMODEL,0,0,
            ff, DFF,0,0, QB, DFF, DMODEL, b1 + (size_t)l*DFF, 1);
        gemm_tc<<<dim3(6,16,1),256,GT_SMEM>>>(ff, DFF,0,0, 0,0,
            w2Th + (size_t)l*DMODEL*DFF, w2Tl + (size_t)l*DMODEL*DFF, DFF,0,0,
            av, DMODEL,0,0, QB, DMODEL, DFF, b2 + (size_t)l*DMODEL, 0);
        add_ln_kernel<<<QB,256>>>(h, av, ln2_g + l*DMODEL, ln2_b + l*DMODEL);
    }

    gemm_tc<<<dim3(79,16,1),256,GT_SMEM>>>(h, DMODEL,0,0, 0,0,
        pTh, pTl, DMODEL,0,0, out, NV,0,0, QB, NV, DMODEL, proj_b, 0);
}

// round 8
// speedup vs baseline: 1.7051x; 1.5217x over previous
#include <cuda_runtime.h>
#include <math.h>
#include <stdint.h>

#define NLAYER 12
#define NH 12
#define DH 64
#define DMODEL 768
#define DFF 3072
#define NV 10000
#define QLEN 512
#define MLEN 512
#define CLEN 32
#define BSZ 4
#define KLEN 1056
#define QB (QLEN*BSZ)
#define KB (KLEN*BSZ)
#define TND (3*NH*DH)
#define ND (NH*DH)
#define NBATCH (BSZ*NH)

#if defined(__CUDA_ARCH_FEAT_SM103_ALL) || defined(__CUDA_ARCH_FEAT_SM100_ALL)
#define HAS_TC 1
#else
#define HAS_TC 0
#endif

// ---------------- scratch ----------------
__device__ float g_h[QB*DMODEL];
__device__ float g_r[KLEN*DMODEL];
__device__ float g_heads[(size_t)KB*TND];
__device__ float g_rk[KLEN*DMODEL];
__device__ float g_ac[(size_t)NBATCH*QLEN*KLEN];
__device__ float g_bd[(size_t)NBATCH*QLEN*KLEN];
__device__ float g_av[QB*DMODEL];
__device__ float g_ff[(size_t)QB*DFF];
__device__ __align__(16) unsigned short g_qkvT_h[(size_t)NLAYER*TND*DMODEL], g_qkvT_l[(size_t)NLAYER*TND*DMODEL];
__device__ __align__(16) unsigned short g_rnT_h[(size_t)NLAYER*ND*DMODEL],  g_rnT_l[(size_t)NLAYER*ND*DMODEL];
__device__ __align__(16) unsigned short g_oT_h[(size_t)NLAYER*DMODEL*ND],   g_oT_l[(size_t)NLAYER*DMODEL*ND];
__device__ __align__(16) unsigned short g_w1T_h[(size_t)NLAYER*DFF*DMODEL], g_w1T_l[(size_t)NLAYER*DFF*DMODEL];
__device__ __align__(16) unsigned short g_w2T_h[(size_t)NLAYER*DMODEL*DFF], g_w2T_l[(size_t)NLAYER*DMODEL*DFF];
__device__ __align__(16) unsigned short g_pT_h[(size_t)NV*DMODEL],          g_pT_l[(size_t)NV*DMODEL];
__device__ __align__(16) unsigned short g_kt_h[(size_t)KB*ND],              g_kt_l[(size_t)KB*ND];
__device__ __align__(16) unsigned short g_rkt_h[(size_t)KLEN*ND],           g_rkt_l[(size_t)KLEN*ND];
__device__ __align__(16) unsigned short g_vt_h[(size_t)NBATCH*DH*KLEN],     g_vt_l[(size_t)NBATCH*DH*KLEN];

// ---------------- PTX helpers ----------------
__device__ __forceinline__ uint32_t smem_u32(const void* p) {
    uint32_t a;
    asm("{ .reg .u64 t; cvta.to.shared.u64 t, %1; cvt.u32.u64 %0, t; }" : "=r"(a) : "l"(p));
    return a;
}
#define MBAR_INIT(a,c) asm volatile("mbarrier.init.shared.b64 [%0], %1;" :: "r"((uint32_t)(a)), "r"((uint32_t)(c)) : "memory")
#define MBAR_INVAL(a)  asm volatile("mbarrier.inval.shared.b64 [%0];" :: "r"((uint32_t)(a)) : "memory")
#define MBAR_WAIT(a,p) do { uint32_t _m=(uint32_t)(a), _p=(uint32_t)(p); \
    asm volatile("{\n\t.reg .pred P1;\n\tWL_%=:\n\t" \
        "mbarrier.try_wait.parity.acquire.cta.shared::cta.b64 P1, [%0], %1, 0x989680;\n\t" \
        "@P1 bra.uni WD_%=;\n\tbra.uni WL_%=;\n\tWD_%=:\n\t}" :: "r"(_m), "r"(_p) : "memory"); } while(0)
#define TC_ALLOC(a,n)   asm volatile("tcgen05.alloc.cta_group::1.sync.aligned.shared::cta.b32 [%0], %1;" :: "r"((uint32_t)(a)), "r"((uint32_t)(n)) : "memory")
#define TC_DEALLOC(t,n) asm volatile("tcgen05.dealloc.cta_group::1.sync.aligned.b32 %0, %1;" :: "r"(t), "r"((uint32_t)(n)))
#define TC_RELINQ()     asm volatile("tcgen05.relinquish_alloc_permit.cta_group::1.sync.aligned;")
#define TC_COMMIT(a)    asm volatile("tcgen05.commit.cta_group::1.mbarrier::arrive::one.shared::cluster.b64 [%0];" :: "r"((uint32_t)(a)) : "memory")
#define TC_WAIT_LD()    asm volatile("tcgen05.wait::ld.sync.aligned;" ::: "memory")
#define TC_FENCE_AFT()  asm volatile("tcgen05.fence::after_thread_sync;" ::: "memory")
#define FENCE_ASYNC()   asm volatile("fence.proxy.async.shared::cta;" ::: "memory")
#define TC_LD_X32(r, ta) asm volatile( \
    "tcgen05.ld.sync.aligned.32x32b.x32.b32 " \
    "{%0,%1,%2,%3,%4,%5,%6,%7,%8,%9,%10,%11,%12,%13,%14,%15," \
    "%16,%17,%18,%19,%20,%21,%22,%23,%24,%25,%26,%27,%28,%29,%30,%31}, [%32];" \
    : "=r"((r)[0]),"=r"((r)[1]),"=r"((r)[2]),"=r"((r)[3]),"=r"((r)[4]),"=r"((r)[5]),"=r"((r)[6]),"=r"((r)[7]), \
      "=r"((r)[8]),"=r"((r)[9]),"=r"((r)[10]),"=r"((r)[11]),"=r"((r)[12]),"=r"((r)[13]),"=r"((r)[14]),"=r"((r)[15]), \
      "=r"((r)[16]),"=r"((r)[17]),"=r"((r)[18]),"=r"((r)[19]),"=r"((r)[20]),"=r"((r)[21]),"=r"((r)[22]),"=r"((r)[23]), \
      "=r"((r)[24]),"=r"((r)[25]),"=r"((r)[26]),"=r"((r)[27]),"=r"((r)[28]),"=r"((r)[29]),"=r"((r)[30]),"=r"((r)[31]) \
    : "r"(ta))

static constexpr uint64_t DESC_BASE =
    (uint64_t(2) << 61) | (uint64_t(1) << 46) | (uint64_t(64) << 32) | (uint64_t(1) << 16);
#define MK_DESC(a) (DESC_BASE | ((uint64_t)((a) >> 4) & 0x3FFF))
#define IDESC_N128 0x8200490u   // f32 accum, bf16 x bf16, M=128, N=128
#define IDESC_N64  0x8100490u   // f32 accum, bf16 x bf16, M=128, N=64

#if HAS_TC
__device__ __forceinline__ void mma_bf16(uint32_t d, uint64_t ad, uint64_t bd,
                                         uint32_t idesc, uint32_t en) {
    asm volatile(
        "{\n\t.reg .pred p;\n\tsetp.ne.u32 p, %4, 0;\n\t"
        "tcgen05.mma.cta_group::1.kind::f16 [%0], %1, %2, %3, {%5, %5, %5, %5}, p;\n\t}"
        :: "r"(d), "l"(ad), "l"(bd), "r"(idesc), "r"(en), "r"(0u) : "memory");
}
#endif

__device__ __forceinline__ void split2(float x0, float x1, unsigned& hi, unsigned& lo) {
    unsigned u0 = __float_as_uint(x0), u1 = __float_as_uint(x1);
    unsigned r0 = (u0 + 0x7fffu + ((u0 >> 16) & 1u)) & 0xffff0000u;
    unsigned r1 = (u1 + 0x7fffu + ((u1 >> 16) & 1u)) & 0xffff0000u;
    hi = (r0 >> 16) | r1;
    unsigned v0 = __float_as_uint(x0 - __uint_as_float(r0));
    unsigned v1 = __float_as_uint(x1 - __uint_as_float(r1));
    unsigned s0 = (v0 + 0x7fffu + ((v0 >> 16) & 1u)) & 0xffff0000u;
    unsigned s1 = (v1 + 0x7fffu + ((v1 >> 16) & 1u)) & 0xffff0000u;
    lo = (s0 >> 16) | s1;
}
__device__ __forceinline__ void split1(float x, unsigned short& h, unsigned short& l) {
    unsigned u = __float_as_uint(x);
    unsigned r = (u + 0x7fffu + ((u >> 16) & 1u)) & 0xffff0000u;
    h = (unsigned short)(r >> 16);
    unsigned v = __float_as_uint(x - __uint_as_float(r));
    l = (unsigned short)((v + 0x7fffu + ((v >> 16) & 1u)) >> 16);
}
__device__ __forceinline__ float bfpair(unsigned short h, unsigned short l) {
    return __uint_as_float((unsigned)h << 16) + __uint_as_float((unsigned)l << 16);
}

__device__ __forceinline__ float warp_sum(float v) {
    #pragma unroll
    for (int o = 16; o; o >>= 1) v += __shfl_xor_sync(0xffffffffu, v, o);
    return v;
}
__device__ __forceinline__ float warp_max(float v) {
    #pragma unroll
    for (int o = 16; o; o >>= 1) v = fmaxf(v, __shfl_xor_sync(0xffffffffu, v, o));
    return v;
}
__device__ __forceinline__ float block_sum(float v, float* red) {
    v = warp_sum(v);
    __syncthreads();
    if ((threadIdx.x & 31) == 0) red[threadIdx.x >> 5] = v;
    __syncthreads();
    float r = 0.f;
    #pragma unroll
    for (int k = 0; k < 8; k++) r += red[k];
    return r;
}

// ---------------- elementwise ----------------
__global__ void embed_kernel(const int* __restrict__ x, const float* __restrict__ emb) {
    int idx = blockIdx.x * 256 + threadIdx.x;
    if (idx >= QB * DMODEL) return;
    int row = idx / DMODEL, d = idx % DMODEL;
    g_h[idx] = emb[(size_t)x[row] * DMODEL + d] * sqrtf(768.0f);
}
__global__ void posemb_kernel() {
    int idx = blockIdx.x * 256 + threadIdx.x;
    if (idx >= KLEN * DMODEL) return;
    int p = idx / DMODEL, d = idx % DMODEL;
    float pos = (float)(KLEN - 1 - p);
    int dd = (d < 384) ? d : d - 384;
    float s = pos / powf(10000.0f, (float)(2 * dd) / 768.0f);
    g_r[idx] = (d < 384) ? sinf(s) : cosf(s);
}

__global__ void __launch_bounds__(256)
transpose_split(const float* __restrict__ src, int ldsrc, int rows, int cols,
                int zq, long srcOffB, long srcOffN,
                unsigned short* __restrict__ dhi, unsigned short* __restrict__ dlo,
                int lddst, long dstOffZ)
{
    __shared__ float t[32][33];
    int z = blockIdx.z, bb = z / zq, nn = z % zq;
    const float* s = src + (long)bb * srcOffB + (long)nn * srcOffN;
    unsigned short* dh = dhi + (long)z * dstOffZ;
    unsigned short* dl = dlo + (long)z * dstOffZ;
    int c0 = blockIdx.x * 32, r0 = blockIdx.y * 32;
    int tx = threadIdx.x & 31, ty = threadIdx.x >> 5;
    #pragma unroll
    for (int dy = 0; dy < 4; dy++) {
        int r = r0 + ty + dy * 8;
        t[ty + dy * 8][tx] = (r < rows && c0 + tx < cols) ? s[(long)r * ldsrc + c0 + tx] : 0.f;
    }
    __syncthreads();
    #pragma unroll
    for (int dy = 0; dy < 4; dy++) {
        int dr = c0 + ty + dy * 8, dc = r0 + tx;
        if (dr < cols && dc < rows) {
            unsigned short h, l;
            split1(t[tx][ty + dy * 8], h, l);
            dh[(long)dr * lddst + dc] = h;
            dl[(long)dr * lddst + dc] = l;
        }
    }
}

__global__ void __launch_bounds__(256)
split_strided(const float* __restrict__ src, int ld, int off, int width, long total,
              unsigned short* __restrict__ dhi, unsigned short* __restrict__ dlo)
{
    long i = ((long)blockIdx.x * 256 + threadIdx.x) * 4;
    if (i >= total) return;
    long row = i / width; int c = (int)(i % width);
    float4 v = *(const float4*)(src + row * ld + off + c);
    unsigned short h, l;
    split1(v.x, h, l); dhi[i] = h; dlo[i] = l;
    split1(v.y, h, l); dhi[i+1] = h; dlo[i+1] = l;
    split1(v.z, h, l); dhi[i+2] = h; dlo[i+2] = l;
    split1(v.w, h, l); dhi[i+3] = h; dlo[i+3] = l;
}

// ---------------- GEMM: C[z] = (A[z]+abias) @ B[z]^T  (B pre-split bf16 hi/lo) ----------------
#define TILE_B 16384
#define GT_SMEM (1024 + 8 * TILE_B)

__global__ void __launch_bounds__(256)
gemm_tc(const float* __restrict__ A, int lda, long aOffB, long aOffN,
        const float* __restrict__ abias, int abStrideN,
        const unsigned short* __restrict__ Bhi, const unsigned short* __restrict__ Blo,
        int ldb, long bOffB, long bOffN,
        float* __restrict__ C, int ldc, long cOffB, long cOffN,
        int M, int N, int K,
        const float* __restrict__ cbias, int relu)
{
    extern __shared__ char smem[];
    const int tid = threadIdx.x;
    const int bb = blockIdx.z / NH, nn = blockIdx.z % NH;
    const int row0 = blockIdx.y * 128, col0 = blockIdx.x * 128;
    const float* Az = A + (long)bb * aOffB + (long)nn * aOffN;
    const unsigned short* Bh = Bhi + (long)bb * bOffB + (long)nn * bOffN;
    const unsigned short* Bl = Blo + (long)bb * bOffB + (long)nn * bOffN;
    float* Cz = C + (long)bb * cOffB + (long)nn * cOffN;
    const float* ab = abias ? (abias + (long)nn * abStrideN) : (const float*)0;

#if HAS_TC
    const uint32_t sb = smem_u32(smem);
    const int wid = tid >> 5, lane = tid & 31;
    const uint32_t idesc = (N <= 64) ? IDESC_N64 : IDESC_N128;
    if (wid == 0) TC_ALLOC(sb, 128);
    if (tid == 0) { MBAR_INIT(sb + 16, 1); MBAR_INIT(sb + 24, 1); }
    __syncthreads();
    uint32_t tmem;
    asm volatile("ld.shared.b32 %0, [%1];" : "=r"(tmem) : "r"(sb));

    const int KT = (K + 63) >> 6;
    int ph0 = 0, ph1 = 0;

    for (int t = 0; t < KT; t++) {
        const int buf = t & 1;
        const uint32_t base = 1024 + (uint32_t)buf * 4 * TILE_B;
        if (t >= 2) {
            if (buf == 0) { MBAR_WAIT(sb + 16, ph0 & 1); ph0++; }
            else          { MBAR_WAIT(sb + 24, ph1 & 1); ph1++; }
        }
        const int k0 = t << 6;
        #pragma unroll
        for (int g = 0; g < 4; g++) {
            int gi = tid + g * 256;
            int r = gi >> 3, kg = gi & 7, kb = k0 + kg * 8;
            float xv[8] = {0,0,0,0,0,0,0,0};
            if (row0 + r < M && kb < K) {
                const float* p = Az + (long)(row0 + r) * lda + kb;
                float4 v0 = *(const float4*)p, v1 = *(const float4*)(p + 4);
                xv[0]=v0.x; xv[1]=v0.y; xv[2]=v0.z; xv[3]=v0.w;
                xv[4]=v1.x; xv[5]=v1.y; xv[6]=v1.z; xv[7]=v1.w;
                if (ab) {
                    #pragma unroll
                    for (int j = 0; j < 8; j++) xv[j] += ab[kb + j];
                }
            }
            unsigned h[4], l[4];
            #pragma unroll
            for (int j = 0; j < 4; j++) split2(xv[2*j], xv[2*j+1], h[j], l[j]);
            uint32_t bo = ((uint32_t)r << 7) + ((uint32_t)kg << 4);
            uint32_t sw = bo ^ ((bo >> 3) & 0x70);
            *(uint4*)(smem + base + sw)          = make_uint4(h[0], h[1], h[2], h[3]);
            *(uint4*)(smem + base + TILE_B + sw) = make_uint4(l[0], l[1], l[2], l[3]);
        }
        #pragma unroll
        for (int g = 0; g < 4; g++) {
            int gi = tid + g * 256;
            int n = gi >> 3, kg = gi & 7, kb = k0 + kg * 8;
            uint4 vh = make_uint4(0,0,0,0), vl = make_uint4(0,0,0,0);
            if (col0 + n < N && kb < K) {
                vh = *(const uint4*)(Bh + (long)(col0 + n) * ldb + kb);
                vl = *(const uint4*)(Bl + (long)(col0 + n) * ldb + kb);
            }
            uint32_t bo = ((uint32_t)n << 7) + ((uint32_t)kg << 4);
            uint32_t sw = bo ^ ((bo >> 3) & 0x70);
            *(uint4*)(smem + base + 2*TILE_B + sw) = vh;
            *(uint4*)(smem + base + 3*TILE_B + sw) = vl;
        }
        __syncthreads();
        if (tid == 0) {
            FENCE_ASYNC();
            uint64_t dAh = MK_DESC(sb + base);
            uint64_t dAl = MK_DESC(sb + base + TILE_B);
            uint64_t dBh = MK_DESC(sb + base + 2*TILE_B);
            uint64_t dBl = MK_DESC(sb + base + 3*TILE_B);
            #pragma unroll
            for (int ks = 0; ks < 4; ks++) {
                mma_bf16(tmem, dAh + ks*2, dBh + ks*2, idesc, (t > 0 || ks > 0) ? 1u : 0u);
                mma_bf16(tmem, dAh + ks*2, dBl + ks*2, idesc, 1u);
                mma_bf16(tmem, dAl + ks*2, dBh + ks*2, idesc, 1u);
            }
            if (buf == 0) TC_COMMIT(sb + 16); else TC_COMMIT(sb + 24);
        }
    }
    if (KT >= 2) {
        if (((KT - 2) & 1) == 0) { MBAR_WAIT(sb + 16, ph0 & 1); ph0++; }
        else                     { MBAR_WAIT(sb + 24, ph1 & 1); ph1++; }
    }
    if (((KT - 1) & 1) == 0) { MBAR_WAIT(sb + 16, ph0 & 1); ph0++; }
    else                     { MBAR_WAIT(sb + 24, ph1 & 1); ph1++; }
    TC_FENCE_AFT();
    __syncthreads();   // staging buffers now free; reuse as epilogue bounce buffer

    // ---- epilogue: TMEM -> smem (stride 132: float4-aligned) -> coalesced global ----
    {
        float* Cs = (float*)(smem + 1024);   // [128][132]
        int sub = wid & 3, ch = wid >> 2;
        int rl = sub * 32 + lane;
        #pragma unroll
        for (int half = 0; half < 2; half++) {
            uint32_t dr[32];
            TC_LD_X32(dr, tmem + (uint32_t)(ch * 64 + half * 32));
            TC_WAIT_LD();
            #pragma unroll
            for (int c = 0; c < 32; c++)
                Cs[rl * 132 + ch * 64 + half * 32 + c] = __uint_as_float(dr[c]);
        }
        __syncthreads();
        for (int i = tid; i < 128 * 32; i += 256) {
            int row = i >> 5, c4 = (i & 31) << 2;
            int r = row0 + row;
            if (r >= M) continue;
            int cg = col0 + c4;
            if (cg >= N) continue;
            float4 v = *(float4*)&Cs[row * 132 + c4];
            float vv[4] = {v.x, v.y, v.z, v.w};
            if (cg + 3 < N) {
                if (cbias) {
                    vv[0] += cbias[cg]; vv[1] += cbias[cg+1];
                    vv[2] += cbias[cg+2]; vv[3] += cbias[cg+3];
                }
                if (relu) {
                    #pragma unroll
                    for (int j = 0; j < 4; j++) vv[j] = fmaxf(vv[j], 0.f);
                }
                *(float4*)&Cz[(long)r * ldc + cg] = make_float4(vv[0], vv[1], vv[2], vv[3]);
            } else {
                #pragma unroll
                for (int j = 0; j < 4; j++) {
                    int c = cg + j;
                    if (c < N) {
                        float w = vv[j];
                        if (cbias) w += cbias[c];
                        if (relu) w = fmaxf(w, 0.f);
                        Cz[(long)r * ldc + c] = w;
                    }
                }
            }
        }
    }
    __syncthreads();
    if (tid == 0) { MBAR_INVAL(sb + 16); MBAR_INVAL(sb + 24); }
    if (wid == 0) { TC_RELINQ(); TC_DEALLOC(tmem, 128); }
#else
    // ---------- SIMT fallback (compute_103 pass; no tcgen05) ----------
    float* As = (float*)smem;
    float* Bs = (float*)smem + 16 * 132;
    const int ty4 = (tid >> 4) << 2, tx4 = (tid & 15) << 2;
    float acc[8][8] = {};
    for (int k0 = 0; k0 < K; k0 += 16) {
        #pragma unroll
        for (int s = 0; s < 2; s++) {
            int idx = tid + s * 256;
            int m = idx >> 2, kc = (idx & 3) << 2;
            float4 v = make_float4(0,0,0,0);
            if (row0 + m < M && k0 + kc < K)
                v = *(const float4*)(Az + (long)(row0 + m) * lda + k0 + kc);
            if (ab && k0 + kc < K) {
                v.x += ab[k0+kc]; v.y += ab[k0+kc+1]; v.z += ab[k0+kc+2]; v.w += ab[k0+kc+3];
            }
            As[(kc+0)*132+m] = v.x; As[(kc+1)*132+m] = v.y;
            As[(kc+2)*132+m] = v.z; As[(kc+3)*132+m] = v.w;
        }
        #pragma unroll
        for (int s = 0; s < 8; s++) {
            int idx = tid + s * 256;
            int n = idx >> 4, kk2 = idx & 15;
            float v = 0.f;
            if (col0 + n < N && k0 + kk2 < K) {
                long o = (long)(col0 + n) * ldb + k0 + kk2;
                v = bfpair(Bh[o], Bl[o]);
            }
            Bs[kk2 * 128 + n] = v;
        }
        __syncthreads();
        #pragma unroll
        for (int k = 0; k < 16; k++) {
            float4 xa0 = *(const float4*)&As[k*132 + ty4];
            float4 xa1 = *(const float4*)&As[k*132 + ty4 + 64];
            float4 xb0 = *(const float4*)&Bs[k*128 + tx4];
            float4 xb1 = *(const float4*)&Bs[k*128 + tx4 + 64];
            float av8[8] = {xa0.x,xa0.y,xa0.z,xa0.w, xa1.x,xa1.y,xa1.z,xa1.w};
            float bv8[8] = {xb0.x,xb0.y,xb0.z,xb0.w, xb1.x,xb1.y,xb1.z,xb1.w};
            #pragma unroll
            for (int i = 0; i < 8; i++)
                #pragma unroll
                for (int j = 0; j < 8; j++) acc[i][j] += av8[i] * bv8[j];
        }
        __syncthreads();
    }
    #pragma unroll
    for (int i = 0; i < 8; i++) {
        int r = row0 + ty4 + ((i < 4) ? i : 60 + i);
        if (r >= M) continue;
        #pragma unroll
        for (int j = 0; j < 8; j++) {
            int c = col0 + tx4 + ((j < 4) ? j : 60 + j);
            if (c >= N) continue;
            float v = acc[i][j];
            if (cbias) v += cbias[c];
            if (relu) v = fmaxf(v, 0.f);
            Cz[(long)r * ldc + c] = v;
        }
    }
#endif
}

// ---------------- softmax (rel-shift folded) ----------------
__global__ void __launch_bounds__(256) softmax_kernel() {
    int i = blockIdx.x, z = blockIdx.y;
    float* row = g_ac + ((size_t)z * QLEN + i) * KLEN;
    const float* bdrow = g_bd + ((size_t)z * QLEN + i) * KLEN;
    int jmax = i + CLEN + MLEN;
    __shared__ float s[KLEN];
    __shared__ float red[8];
    int tid = threadIdx.x;
    float lmax = -3.0e38f;
    for (int j = tid; j <= jmax; j += 256) {
        float v = (row[j] + bdrow[j + QLEN - 1 - i]) * 0.125f;
        s[j] = v;
        lmax = fmaxf(lmax, v);
    }
    lmax = warp_max(lmax);
    __syncthreads();
    if ((tid & 31) == 0) red[tid >> 5] = lmax;
    __syncthreads();
    float m = red[0];
    #pragma unroll
    for (int k = 1; k < 8; k++) m = fmaxf(m, red[k]);
    float lsum = 0.f;
    for (int j = tid; j <= jmax; j += 256) { float e = expf(s[j] - m); s[j] = e; lsum += e; }
    float inv = 1.0f / block_sum(lsum, red);
    __syncthreads();
    for (int j = tid; j < KLEN; j += 256)
        row[j] = (j <= jmax) ? s[j] * inv : 0.0f;
}

__global__ void __launch_bounds__(256)
add_ln_kernel(float* __restrict__ h, const float* __restrict__ res,
              const float* __restrict__ g, const float* __restrict__ b)
{
    __shared__ float red[8];
    int row = blockIdx.x, tid = threadIdx.x;
    size_t base = (size_t)row * DMODEL;
    float x0 = h[base + tid]       + res[base + tid];
    float x1 = h[base + tid + 256] + res[base + tid + 256];
    float x2 = h[base + tid + 512] + res[base + tid + 512];
    float mean = block_sum(x0 + x1 + x2, red) * (1.0f / 768.0f);
    float d0 = x0 - mean, d1 = x1 - mean, d2 = x2 - mean;
    float inv = rsqrtf(block_sum(d0*d0 + d1*d1 + d2*d2, red) * (1.0f / 768.0f) + 1e-5f);
    h[base + tid]       = d0 * inv * g[tid]       + b[tid];
    h[base + tid + 256] = d1 * inv * g[tid + 256] + b[tid + 256];
    h[base + tid + 512] = d2 * inv * g[tid + 512] + b[tid + 512];
}

// ---------------- host ----------------
extern "C" void kernel_launch(void* const* d_in, const int* in_sizes, int n_in,
                              void* d_out, int out_size)
{
    const int*   x         = (const int*)  d_in[0];
    const float* condition = (const float*)d_in[1];
    const float* mems      = (const float*)d_in[2];
    const float* emb       = (const float*)d_in[3];
    const float* qkv_w     = (const float*)d_in[4];
    const float* r_net_w   = (const float*)d_in[5];
    const float* o_w       = (const float*)d_in[6];
    const float* ln1_g     = (const float*)d_in[7];
    const float* ln1_b     = (const float*)d_in[8];
    const float* w1        = (const float*)d_in[9];
    const float* b1        = (const float*)d_in[10];
    const float* w2        = (const float*)d_in[11];
    const float* b2        = (const float*)d_in[12];
    const float* ln2_g     = (const float*)d_in[13];
    const float* ln2_b     = (const float*)d_in[14];
    const float* r_w_bias  = (const float*)d_in[15];
    const float* r_r_bias  = (const float*)d_in[16];
    const float* proj_w    = (const float*)d_in[17];
    const float* proj_b    = (const float*)d_in[18];
    float* out = (float*)d_out;

    cudaFuncSetAttribute(gemm_tc, cudaFuncAttributeMaxDynamicSharedMemorySize, GT_SMEM);

    float *h, *r, *heads, *rk, *ac, *bd, *av, *ff;
    unsigned short *qkvTh,*qkvTl,*rnTh,*rnTl,*oTh,*oTl,*w1Th,*w1Tl,*w2Th,*w2Tl,*pTh,*pTl,*kth,*ktl,*rkth,*rktl,*vth,*vtl;
#define SYM(p, s) cudaGetSymbolAddress((void**)&p, s)
    SYM(h,g_h); SYM(r,g_r); SYM(heads,g_heads); SYM(rk,g_rk); SYM(ac,g_ac); SYM(bd,g_bd);
    SYM(av,g_av); SYM(ff,g_ff);
    SYM(qkvTh,g_qkvT_h); SYM(qkvTl,g_qkvT_l); SYM(rnTh,g_rnT_h); SYM(rnTl,g_rnT_l);
    SYM(oTh,g_oT_h); SYM(oTl,g_oT_l); SYM(w1Th,g_w1T_h); SYM(w1Tl,g_w1T_l);
    SYM(w2Th,g_w2T_h); SYM(w2Tl,g_w2T_l); SYM(pTh,g_pT_h); SYM(pTl,g_pT_l);
    SYM(kth,g_kt_h); SYM(ktl,g_kt_l); SYM(rkth,g_rkt_h); SYM(rktl,g_rkt_l);
    SYM(vth,g_vt_h); SYM(vtl,g_vt_l);
#undef SYM

    // launch order chosen so ncu (-s 5 -c 1) captures launch #6 = L0 qkv gemm_tc
    embed_kernel<<<(QB*DMODEL+255)/256, 256>>>(x, emb);                                          // 1
    posemb_kernel<<<(KLEN*DMODEL+255)/256, 256>>>();                                             // 2
    transpose_split<<<dim3(72,24,NLAYER),256>>>(qkv_w, TND, DMODEL, TND, 1, (long)DMODEL*TND, 0, qkvTh, qkvTl, DMODEL, (long)TND*DMODEL);  // 3
    transpose_split<<<dim3(24,24,NLAYER),256>>>(r_net_w, ND, DMODEL, ND, 1, (long)DMODEL*ND, 0, rnTh, rnTl, DMODEL, (long)ND*DMODEL);      // 4
    transpose_split<<<dim3(24,24,NLAYER),256>>>(o_w, DMODEL, ND, DMODEL, 1, (long)ND*DMODEL, 0, oTh, oTl, ND, (long)DMODEL*ND);            // 5

    int first = 1;
    for (int l = 0; l < NLAYER; l++) {
        const unsigned short* Wh = qkvTh + (size_t)l*TND*DMODEL;
        const unsigned short* Wl = qkvTl + (size_t)l*TND*DMODEL;
        float* q = heads + (size_t)(CLEN+MLEN)*BSZ*TND;

        gemm_tc<<<dim3(18,16,1),256,GT_SMEM>>>(h, DMODEL,0,0, 0,0, Wh, Wl, DMODEL,0,0,           // 6 (captured)
            q, TND,0,0, QB, TND, DMODEL, 0,0);
        if (first) {
            transpose_split<<<dim3(96,24,NLAYER),256>>>(w1, DFF, DMODEL, DFF, 1, (long)DMODEL*DFF, 0, w1Th, w1Tl, DMODEL, (long)DFF*DMODEL);
            transpose_split<<<dim3(24,96,NLAYER),256>>>(w2, DMODEL, DFF, DMODEL, 1, (long)DFF*DMODEL, 0, w2Th, w2Tl, DFF, (long)DMODEL*DFF);
            transpose_split<<<dim3(313,24,1),256>>>(proj_w, NV, DMODEL, NV, 1, 0, 0, pTh, pTl, DMODEL, 0);
            first = 0;
        }
        gemm_tc<<<dim3(12,1,1),256,GT_SMEM>>>(condition, DMODEL,0,0, 0,0,
            Wh + (size_t)ND*DMODEL, Wl + (size_t)ND*DMODEL, DMODEL,0,0,
            heads + ND, TND,0,0, CLEN*BSZ, 2*ND, DMODEL, 0,0);
        gemm_tc<<<dim3(12,16,1),256,GT_SMEM>>>(mems + (size_t)l*MLEN*BSZ*DMODEL, DMODEL,0,0, 0,0,
            Wh + (size_t)ND*DMODEL, Wl + (size_t)ND*DMODEL, DMODEL,0,0,
            heads + (size_t)CLEN*BSZ*TND + ND, TND,0,0, MLEN*BSZ, 2*ND, DMODEL, 0,0);
        gemm_tc<<<dim3(6,9,1),256,GT_SMEM>>>(r, DMODEL,0,0, 0,0,
            rnTh + (size_t)l*ND*DMODEL, rnTl + (size_t)l*ND*DMODEL, DMODEL,0,0,
            rk, ND,0,0, KLEN, ND, DMODEL, 0,0);

        split_strided<<<((long)KB*ND/4+255)/256,256>>>(heads, TND, ND, ND, (long)KB*ND, kth, ktl);
        split_strided<<<((long)KLEN*ND/4+255)/256,256>>>(rk, ND, 0, ND, (long)KLEN*ND, rkth, rktl);
        transpose_split<<<dim3(2,33,NBATCH),256>>>(heads + 2*ND, BSZ*TND, KLEN, DH, NH, TND, DH,
            vth, vtl, KLEN, (long)DH*KLEN);

        gemm_tc<<<dim3(9,4,NBATCH),256,GT_SMEM>>>(q, BSZ*TND, TND, DH, r_w_bias, DH,
            kth, ktl, BSZ*ND, ND, DH,
            ac, KLEN, (long)NH*QLEN*KLEN, (long)QLEN*KLEN, QLEN, KLEN, DH, 0,0);
        gemm_tc<<<dim3(9,4,NBATCH),256,GT_SMEM>>>(q, BSZ*TND, TND, DH, r_r_bias, DH,
            rkth, rktl, ND, 0, DH,
            bd, KLEN, (long)NH*QLEN*KLEN, (long)QLEN*KLEN, QLEN, KLEN, DH, 0,0);

        softmax_kernel<<<dim3(QLEN,NBATCH),256>>>();

        gemm_tc<<<dim3(1,4,NBATCH),256,GT_SMEM>>>(ac, KLEN, (long)NH*QLEN*KLEN, (long)QLEN*KLEN, 0,0,
            vth, vtl, KLEN, (long)NH*DH*KLEN, (long)DH*KLEN,
            av, BSZ*DMODEL, DMODEL, DH, QLEN, DH, KLEN, 0,0);

        gemm_tc<<<dim3(6,16,1),256,GT_SMEM>>>(av, DMODEL,0,0, 0,0,
            oTh + (size_t)l*DMODEL*ND, oTl + (size_t)l*DMODEL*ND, ND,0,0,
            ff, DMODEL,0,0, QB, DMODEL, ND, 0,0);
        add_ln_kernel<<<QB,256>>>(h, ff, ln1_g + l*DMODEL, ln1_b + l*DMODEL);

        gemm_tc<<<dim3(24,16,1),256,GT_SMEM>>>(h, DMODEL,0,0, 0,0,
            w1Th + (size_t)l*DFF*DMODEL, w1Tl + (size_t)l*DFF*DMODEL, DMODEL,0,0,
            ff, DFF,0,0, QB, DFF, DMODEL, b1 + (size_t)l*DFF, 1);
        gemm_tc<<<dim3(6,16,1),256,GT_SMEM>>>(ff, DFF,0,0, 0,0,
            w2Th + (size_t)l*DMODEL*DFF, w2Tl + (size_t)l*DMODEL*DFF, DFF,0,0,
            av, DMODEL,0,0, QB, DMODEL, DFF, b2 + (size_t)l*DMODEL, 0);
        add_ln_kernel<<<QB,256>>>(h, av, ln2_g + l*DMODEL, ln2_b + l*DMODEL);
    }

    gemm_tc<<<dim3(79,16,1),256,GT_SMEM>>>(h, DMODEL,0,0, 0,0,
        pTh, pTl, DMODEL,0,0, out, NV,0,0, QB, NV, DMODEL, proj_b, 0);
}